// round 16
// baseline (speedup 1.0000x reference)
#include <cuda_runtime.h>

// Spline1DInterpolant, compact-support closed form. FINAL (converged).
//
// Math: s = (x-a)*n/(b-a); ib = floor(s); f = s-ib in [0,1); g = 1-f.
//   y = c[ib]*g^3 + c[ib+1]*(4-6f^2+3f^3) + c[ib+2]*(4-6g^2+3g^3) + c[ib+3]*f^3
// All other basis terms are exactly 0 (compact support t<2): the reference's
// dense [B,4096] matvec collapses to 4 taps per query.
//
// Gather: the 4 taps are consecutive -> fetch 2 aligned float4 blocks and
// select window [r..r+3], r = ib&3, via SELs (2 LDGs instead of 4 scattered).
// Edge clamp of the second block only aliases positions whose weight is
// exactly 0 (s == n boundary).
//
// Convergence evidence (10 passing variants, rounds 1-15):
//   - wall pinned 6.5-6.9us: graph-replay fixed cost, kernel-content
//     invariant across scalar/float4, branched/branch-free, 32-256 CTA
//     grids, div/fast-div, guarded/unguarded.
//   - chip time 5.34 -> ~4.6us (+-0.3us run-to-run noise, calibrated by an
//     identical-binary re-bench in R15) via: branch-free clamped indices,
//     float4-pair window gather, 128x128 single-wave grid, __ldg +
//     x-load-first chain ordering, __fdividef.
//   - DRAM 0.2%, all pipes <2%, issue ~2-3% throughout. Residual chip time
//     is ~4.2us launch/prologue/drain floor + ~0.35us true latency chain
//     (x LDG -> FMA -> MUFU.RCP -> F2I -> gather -> 4xFMA -> STG).
//   No source-level lever remains below the launch floor.

__global__ __launch_bounds__(128, 1)
void spline1d_kernel(const float* __restrict__ x,
                     const float* __restrict__ a,
                     const float* __restrict__ b,
                     const float* __restrict__ n,
                     const float4* __restrict__ c4,
                     float* __restrict__ out,
                     int C4) {
    int tid = blockIdx.x * blockDim.x + threadIdx.x;   // grid covers B exactly

    // Unique per-thread load first: longest latency chain starts at issue 0;
    // the three uniform loads issue in parallel and broadcast-hit L1.
    float xv = __ldg(&x[tid]);
    float av = __ldg(&a[0]);
    float bv = __ldg(&b[0]);
    float nv = __ldg(&n[0]);

    float inv_h = __fdividef(nv, bv - av);  // bare MUFU.RCP path, ~2ulp
    float s = (xv - av) * inv_h;            // s in [0, n], n = 4*C4 - 3

    int ib = __float2int_rd(s);             // floor; s >= 0 -> ib >= 0
    float f = s - (float)ib;                // [0,1)
    float g = 1.0f - f;

    float f2 = f * f, f3 = f2 * f;
    float g2 = g * g, g3 = g2 * g;

    float w0 = g3;
    float w1 = fmaf(3.0f, f3, fmaf(-6.0f, f2, 4.0f));
    float w2 = fmaf(3.0f, g3, fmaf(-6.0f, g2, 4.0f));
    float w3 = f3;

    int base  = ib >> 2;                    // 0 .. C4-1
    int r     = ib & 3;
    int base1 = min(base + 1, C4 - 1);      // aliased lanes carry weight 0

    float4 q0 = c4[base];                   // two independent gathers,
    float4 q1 = c4[base1];                  // one L1tex roundtrip

    float d0 = (r == 0) ? q0.x : (r == 1) ? q0.y : (r == 2) ? q0.z : q0.w;
    float d1 = (r == 0) ? q0.y : (r == 1) ? q0.z : (r == 2) ? q0.w : q1.x;
    float d2 = (r == 0) ? q0.z : (r == 1) ? q0.w : (r == 2) ? q1.x : q1.y;
    float d3 = (r == 0) ? q0.w : (r == 1) ? q1.x : (r == 2) ? q1.y : q1.z;

    float acc = d0 * w0;
    acc = fmaf(d1, w1, acc);
    acc = fmaf(d2, w2, acc);
    acc = fmaf(d3, w3, acc);
    out[tid] = acc;
}

// Fallback with tail guard for shapes not divisible by the block size.
__global__ __launch_bounds__(128, 1)
void spline1d_kernel_guarded(const float* __restrict__ x,
                             const float* __restrict__ a,
                             const float* __restrict__ b,
                             const float* __restrict__ n,
                             const float4* __restrict__ c4,
                             float* __restrict__ out,
                             int B, int C4) {
    int tid = blockIdx.x * blockDim.x + threadIdx.x;
    if (tid >= B) return;

    float xv = __ldg(&x[tid]);
    float av = __ldg(&a[0]);
    float bv = __ldg(&b[0]);
    float nv = __ldg(&n[0]);

    float inv_h = __fdividef(nv, bv - av);
    float s = (xv - av) * inv_h;

    int ib = __float2int_rd(s);
    float f = s - (float)ib;
    float g = 1.0f - f;

    float f2 = f * f, f3 = f2 * f;
    float g2 = g * g, g3 = g2 * g;

    float w0 = g3;
    float w1 = fmaf(3.0f, f3, fmaf(-6.0f, f2, 4.0f));
    float w2 = fmaf(3.0f, g3, fmaf(-6.0f, g2, 4.0f));
    float w3 = f3;

    int base  = ib >> 2;
    int r     = ib & 3;
    int base1 = min(base + 1, C4 - 1);

    float4 q0 = c4[base];
    float4 q1 = c4[base1];

    float d0 = (r == 0) ? q0.x : (r == 1) ? q0.y : (r == 2) ? q0.z : q0.w;
    float d1 = (r == 0) ? q0.y : (r == 1) ? q0.z : (r == 2) ? q0.w : q1.x;
    float d2 = (r == 0) ? q0.z : (r == 1) ? q0.w : (r == 2) ? q1.x : q1.y;
    float d3 = (r == 0) ? q0.w : (r == 1) ? q1.x : (r == 2) ? q1.y : q1.z;

    float acc = d0 * w0;
    acc = fmaf(d1, w1, acc);
    acc = fmaf(d2, w2, acc);
    acc = fmaf(d3, w3, acc);
    out[tid] = acc;
}

extern "C" void kernel_launch(void* const* d_in, const int* in_sizes, int n_in,
                              void* d_out, int out_size) {
    const float* x = (const float*)d_in[0];
    const float* a = (const float*)d_in[1];
    const float* b = (const float*)d_in[2];
    const float* n = (const float*)d_in[3];
    const float* c = (const float*)d_in[4];
    float* out = (float*)d_out;

    int B = in_sizes[0];      // 16384
    int C = in_sizes[4];      // 4096 (divisible by 4)

    const int threads = 128;
    if ((B % threads) == 0) {
        spline1d_kernel<<<B / threads, threads>>>(x, a, b, n, (const float4*)c,
                                                  out, C >> 2);
    } else {
        spline1d_kernel_guarded<<<(B + threads - 1) / threads, threads>>>(
            x, a, b, n, (const float4*)c, out, B, C >> 2);
    }
}

// round 17
// speedup vs baseline: 1.0588x; 1.0588x over previous
#include <cuda_runtime.h>

// Spline1DInterpolant, compact-support closed form. FINAL (converged, held).
//
// Math: s = (x-a)*n/(b-a); ib = floor(s); f = s-ib in [0,1); g = 1-f.
//   y = c[ib]*g^3 + c[ib+1]*(4-6f^2+3f^3) + c[ib+2]*(4-6g^2+3g^3) + c[ib+3]*f^3
// All other basis terms are exactly 0 (compact support t<2): the reference's
// dense [B,4096] matvec collapses to 4 taps per query.
//
// Gather: the 4 taps are consecutive -> fetch 2 aligned float4 blocks and
// select window [r..r+3], r = ib&3, via SELs (2 LDGs instead of 4 scattered).
// Edge clamp of the second block only aliases positions whose weight is
// exactly 0 (s == n boundary).
//
// Convergence evidence (11 bench runs, rounds 1-16):
//   - wall pinned 6.5-6.9us: graph-replay fixed cost, kernel-content
//     invariant across scalar/float4, branched/branch-free, 32-256 CTA
//     grids, div/fast-div, guarded/unguarded. Two identical-binary
//     re-benches (R15, R16) span the full band -> it is noise.
//   - chip time 5.34 -> ~4.7us center (+-0.3us noise) via: branch-free
//     clamped indices, float4-pair window gather, 128x128 single-wave grid,
//     __ldg + x-load-first ordering, __fdividef.
//   - DRAM 0.2%, all pipes <0.5%, issue ~2.4%: no resource is contended.
//     Residual = ~4.2us launch/prologue/drain floor + ~0.35us true latency
//     chain (x LDG -> FMA -> MUFU.RCP -> F2I -> gather -> 4xFMA -> STG).
//   No source-level lever remains below the launch floor.

__global__ __launch_bounds__(128, 1)
void spline1d_kernel(const float* __restrict__ x,
                     const float* __restrict__ a,
                     const float* __restrict__ b,
                     const float* __restrict__ n,
                     const float4* __restrict__ c4,
                     float* __restrict__ out,
                     int C4) {
    int tid = blockIdx.x * blockDim.x + threadIdx.x;   // grid covers B exactly

    // Unique per-thread load first: longest latency chain starts at issue 0;
    // the three uniform loads issue in parallel and broadcast-hit L1.
    float xv = __ldg(&x[tid]);
    float av = __ldg(&a[0]);
    float bv = __ldg(&b[0]);
    float nv = __ldg(&n[0]);

    float inv_h = __fdividef(nv, bv - av);  // bare MUFU.RCP path, ~2ulp
    float s = (xv - av) * inv_h;            // s in [0, n], n = 4*C4 - 3

    int ib = __float2int_rd(s);             // floor; s >= 0 -> ib >= 0
    float f = s - (float)ib;                // [0,1)
    float g = 1.0f - f;

    float f2 = f * f, f3 = f2 * f;
    float g2 = g * g, g3 = g2 * g;

    float w0 = g3;
    float w1 = fmaf(3.0f, f3, fmaf(-6.0f, f2, 4.0f));
    float w2 = fmaf(3.0f, g3, fmaf(-6.0f, g2, 4.0f));
    float w3 = f3;

    int base  = ib >> 2;                    // 0 .. C4-1
    int r     = ib & 3;
    int base1 = min(base + 1, C4 - 1);      // aliased lanes carry weight 0

    float4 q0 = c4[base];                   // two independent gathers,
    float4 q1 = c4[base1];                  // one L1tex roundtrip

    float d0 = (r == 0) ? q0.x : (r == 1) ? q0.y : (r == 2) ? q0.z : q0.w;
    float d1 = (r == 0) ? q0.y : (r == 1) ? q0.z : (r == 2) ? q0.w : q1.x;
    float d2 = (r == 0) ? q0.z : (r == 1) ? q0.w : (r == 2) ? q1.x : q1.y;
    float d3 = (r == 0) ? q0.w : (r == 1) ? q1.x : (r == 2) ? q1.y : q1.z;

    float acc = d0 * w0;
    acc = fmaf(d1, w1, acc);
    acc = fmaf(d2, w2, acc);
    acc = fmaf(d3, w3, acc);
    out[tid] = acc;
}

// Fallback with tail guard for shapes not divisible by the block size.
__global__ __launch_bounds__(128, 1)
void spline1d_kernel_guarded(const float* __restrict__ x,
                             const float* __restrict__ a,
                             const float* __restrict__ b,
                             const float* __restrict__ n,
                             const float4* __restrict__ c4,
                             float* __restrict__ out,
                             int B, int C4) {
    int tid = blockIdx.x * blockDim.x + threadIdx.x;
    if (tid >= B) return;

    float xv = __ldg(&x[tid]);
    float av = __ldg(&a[0]);
    float bv = __ldg(&b[0]);
    float nv = __ldg(&n[0]);

    float inv_h = __fdividef(nv, bv - av);
    float s = (xv - av) * inv_h;

    int ib = __float2int_rd(s);
    float f = s - (float)ib;
    float g = 1.0f - f;

    float f2 = f * f, f3 = f2 * f;
    float g2 = g * g, g3 = g2 * g;

    float w0 = g3;
    float w1 = fmaf(3.0f, f3, fmaf(-6.0f, f2, 4.0f));
    float w2 = fmaf(3.0f, g3, fmaf(-6.0f, g2, 4.0f));
    float w3 = f3;

    int base  = ib >> 2;
    int r     = ib & 3;
    int base1 = min(base + 1, C4 - 1);

    float4 q0 = c4[base];
    float4 q1 = c4[base1];

    float d0 = (r == 0) ? q0.x : (r == 1) ? q0.y : (r == 2) ? q0.z : q0.w;
    float d1 = (r == 0) ? q0.y : (r == 1) ? q0.z : (r == 2) ? q0.w : q1.x;
    float d2 = (r == 0) ? q0.z : (r == 1) ? q0.w : (r == 2) ? q1.x : q1.y;
    float d3 = (r == 0) ? q0.w : (r == 1) ? q1.x : (r == 2) ? q1.y : q1.z;

    float acc = d0 * w0;
    acc = fmaf(d1, w1, acc);
    acc = fmaf(d2, w2, acc);
    acc = fmaf(d3, w3, acc);
    out[tid] = acc;
}

extern "C" void kernel_launch(void* const* d_in, const int* in_sizes, int n_in,
                              void* d_out, int out_size) {
    const float* x = (const float*)d_in[0];
    const float* a = (const float*)d_in[1];
    const float* b = (const float*)d_in[2];
    const float* n = (const float*)d_in[3];
    const float* c = (const float*)d_in[4];
    float* out = (float*)d_out;

    int B = in_sizes[0];      // 16384
    int C = in_sizes[4];      // 4096 (divisible by 4)

    const int threads = 128;
    if ((B % threads) == 0) {
        spline1d_kernel<<<B / threads, threads>>>(x, a, b, n, (const float4*)c,
                                                  out, C >> 2);
    } else {
        spline1d_kernel_guarded<<<(B + threads - 1) / threads, threads>>>(
            x, a, b, n, (const float4*)c, out, B, C >> 2);
    }
}